// round 7
// baseline (speedup 1.0000x reference)
#include <cuda_runtime.h>
#include <cuda_bf16.h>
#include <cstdint>

#define BATCH 4096
#define DIM   256
#define NNEG  32768
#define FUSED_BLOCKS 2048

// ---------------- scratch (device globals; no allocs allowed) ----------------
__device__ float g_rowsum[BATCH];
__device__ float g_colsum[BATCH];
__device__ float g_negsum[BATCH];
__device__ float g_diag[BATCH];
__device__ int   g_off[BATCH];          // exclusive prefix of counts
__device__ unsigned int g_done;         // retirement counter
__device__ __nv_bfloat16 g_qb[BATCH * DIM];
__device__ __nv_bfloat16 g_pb[BATCH * DIM];

__device__ __forceinline__ uint32_t smem_u32(const void* p) {
    uint32_t a;
    asm("{ .reg .u64 t; cvta.to.shared.u64 t, %1; cvt.u32.u64 %0, t; }" : "=r"(a) : "l"(p));
    return a;
}

__device__ __forceinline__ float inv_tau(const float* log_tau) {
    float t = expf(log_tau[0]);
    t = fminf(fmaxf(t, 1e-4f), 1.0f);
    return 1.0f / t;
}

// ---------------- setup: fp32->bf16 convert + zero + (block 256) offsets scan ----------------
// Blocks 0..255: 1024 threads, each converts one float4 of q and p.
// Block 256: 1024 threads compute exclusive-prefix offsets of counts.
__global__ void convert_scan_kernel(const float* __restrict__ q, const float* __restrict__ p,
                                    const int* __restrict__ counts) {
    int tid = threadIdx.x;
    if (blockIdx.x < 256) {
        int i = blockIdx.x * 1024 + tid;  // over BATCH*DIM/4 = 262144
        if (i < BATCH) { g_rowsum[i] = 0.f; g_colsum[i] = 0.f; g_negsum[i] = 0.f; }
        if (i == 0) g_done = 0u;
        const float4 qa = ((const float4*)q)[i];
        const float4 pa = ((const float4*)p)[i];
        __nv_bfloat162* qd = (__nv_bfloat162*)g_qb;
        __nv_bfloat162* pd = (__nv_bfloat162*)g_pb;
        qd[i * 2 + 0] = __floats2bfloat162_rn(qa.x, qa.y);
        qd[i * 2 + 1] = __floats2bfloat162_rn(qa.z, qa.w);
        pd[i * 2 + 0] = __floats2bfloat162_rn(pa.x, pa.y);
        pd[i * 2 + 1] = __floats2bfloat162_rn(pa.z, pa.w);
        return;
    }
    // ---- scan block: offsets only, fully parallel ----
    __shared__ int wsum[32];
    int lane = tid & 31, w = tid >> 5;
    int4 c4 = ((const int4*)counts)[tid];          // counts[4t .. 4t+3]
    int run = c4.x + c4.y + c4.z + c4.w;
    int incl = run;
    #pragma unroll
    for (int m = 1; m < 32; m <<= 1) {
        int t = __shfl_up_sync(0xffffffffu, incl, m);
        if (lane >= m) incl += t;
    }
    if (lane == 31) wsum[w] = incl;
    __syncthreads();
    if (tid < 32) {
        int v = wsum[tid];
        int s = v;
        #pragma unroll
        for (int m = 1; m < 32; m <<= 1) {
            int t = __shfl_up_sync(0xffffffffu, s, m);
            if (tid >= m) s += t;
        }
        wsum[tid] = s - v;   // exclusive warp base
    }
    __syncthreads();
    int excl = incl - run + wsum[w];
    int4 o;
    o.x = excl;
    o.y = o.x + c4.x;
    o.z = o.y + c4.y;
    o.w = o.z + c4.z;
    ((int4*)g_off)[tid] = o;
}

// ---------------- fused sim(MMA) + neg kernel + inline finalize ----------------
// Even blockIdx -> sim 128x128 tile; odd blockIdx -> 32 negatives.
// Last block to retire runs the final loss reduction.
#define STRIDE     144
#define TILE_BYTES (128 * STRIDE)
#define BUF_BYTES  (2 * TILE_BYTES)
#define SM_TOTAL   (2 * BUF_BYTES)     // 73728

#define CP_COMMIT() asm volatile("cp.async.commit_group;" ::: "memory")

__device__ __forceinline__ void load_chunk(uint32_t sb, const char* qa, const char* pa,
                                           int chunk, int buf, int tid) {
    uint32_t base = sb + buf * BUF_BYTES;
    #pragma unroll
    for (int it = 0; it < 4; it++) {
        int idx = it * 256 + tid;
        int r = idx >> 3, s = idx & 7;
        uint32_t dst = base + r * STRIDE + s * 16;
        const char* srcA = qa + r * 512 + chunk * 128 + s * 16;
        const char* srcB = pa + r * 512 + chunk * 128 + s * 16;
        asm volatile("cp.async.cg.shared.global [%0], [%1], 16;" :: "r"(dst), "l"(srcA));
        asm volatile("cp.async.cg.shared.global [%0], [%1], 16;"
                     :: "r"(dst + TILE_BYTES), "l"(srcB));
    }
}

__device__ __forceinline__ void compute_chunk(uint32_t sb, int buf, int warpM, int warpN,
                                              int lane, float acc[2][8][4]) {
    uint32_t base  = sb + buf * BUF_BYTES;
    uint32_t aAddr = base + (uint32_t)(warpM + (lane & 15)) * STRIDE
                   + (uint32_t)(lane >> 4) * 16;
    uint32_t bAddr = base + TILE_BYTES
                   + (uint32_t)(warpN + (lane & 7) + ((lane >> 4) << 3)) * STRIDE
                   + (uint32_t)((lane >> 3) & 1) * 16;
    #pragma unroll
    for (int s = 0; s < 4; s++) {
        const uint32_t koff = (uint32_t)s * 32;
        uint32_t a[2][4];
        #pragma unroll
        for (int mi = 0; mi < 2; mi++) {
            asm volatile("ldmatrix.sync.aligned.m8n8.x4.shared.b16 {%0,%1,%2,%3}, [%4];"
                : "=r"(a[mi][0]), "=r"(a[mi][1]), "=r"(a[mi][2]), "=r"(a[mi][3])
                : "r"(aAddr + mi * (16 * STRIDE) + koff));
        }
        uint32_t b[4][4];
        #pragma unroll
        for (int nb = 0; nb < 4; nb++) {
            asm volatile("ldmatrix.sync.aligned.m8n8.x4.shared.b16 {%0,%1,%2,%3}, [%4];"
                : "=r"(b[nb][0]), "=r"(b[nb][1]), "=r"(b[nb][2]), "=r"(b[nb][3])
                : "r"(bAddr + nb * (16 * STRIDE) + koff));
        }
        #pragma unroll
        for (int mi = 0; mi < 2; mi++)
            #pragma unroll
            for (int nb = 0; nb < 4; nb++)
                #pragma unroll
                for (int sub = 0; sub < 2; sub++) {
                    float* d = acc[mi][nb * 2 + sub];
                    asm volatile(
                        "mma.sync.aligned.m16n8k16.row.col.f32.bf16.bf16.f32 "
                        "{%0,%1,%2,%3}, {%4,%5,%6,%7}, {%8,%9}, {%0,%1,%2,%3};"
                        : "+f"(d[0]), "+f"(d[1]), "+f"(d[2]), "+f"(d[3])
                        : "r"(a[mi][0]), "r"(a[mi][1]), "r"(a[mi][2]), "r"(a[mi][3]),
                          "r"(b[nb][sub * 2]), "r"(b[nb][sub * 2 + 1]));
                }
    }
}

__device__ void sim_block(uint32_t sb, int tileIdx, const float* __restrict__ log_tau) {
    const int tid  = threadIdx.x;
    const int wid  = tid >> 5;
    const int lane = tid & 31;
    const int row0 = (tileIdx >> 5) * 128;
    const int col0 = (tileIdx & 31) * 128;
    const int warpM = (wid >> 1) * 32;
    const int warpN = (wid & 1) * 64;

    const char* qa = (const char*)(g_qb + (size_t)row0 * DIM);
    const char* pa = (const char*)(g_pb + (size_t)col0 * DIM);

    float acc[2][8][4];
    #pragma unroll
    for (int mi = 0; mi < 2; mi++)
        #pragma unroll
        for (int ni = 0; ni < 8; ni++)
            #pragma unroll
            for (int r = 0; r < 4; r++) acc[mi][ni][r] = 0.f;

    load_chunk(sb, qa, pa, 0, 0, tid); CP_COMMIT();
    load_chunk(sb, qa, pa, 1, 1, tid); CP_COMMIT();

    asm volatile("cp.async.wait_group 1;" ::: "memory");
    __syncthreads();
    compute_chunk(sb, 0, warpM, warpN, lane, acc);
    __syncthreads();
    load_chunk(sb, qa, pa, 2, 0, tid); CP_COMMIT();

    asm volatile("cp.async.wait_group 1;" ::: "memory");
    __syncthreads();
    compute_chunk(sb, 1, warpM, warpN, lane, acc);
    __syncthreads();
    load_chunk(sb, qa, pa, 3, 1, tid); CP_COMMIT();

    asm volatile("cp.async.wait_group 1;" ::: "memory");
    __syncthreads();
    compute_chunk(sb, 0, warpM, warpN, lane, acc);

    asm volatile("cp.async.wait_group 0;" ::: "memory");
    __syncthreads();
    compute_chunk(sb, 1, warpM, warpN, lane, acc);

    // ---- epilogue ----
    const float scale = inv_tau(log_tau);
    const int g   = lane >> 2;
    const int tig = lane & 3;
    const bool diagBlk = (row0 == col0);

    float rsum[4];
    #pragma unroll
    for (int k = 0; k < 4; k++) rsum[k] = 0.f;
    float csum[8][2];
    #pragma unroll
    for (int ni = 0; ni < 8; ni++) { csum[ni][0] = 0.f; csum[ni][1] = 0.f; }

    #pragma unroll
    for (int mi = 0; mi < 2; mi++)
        #pragma unroll
        for (int ni = 0; ni < 8; ni++)
            #pragma unroll
            for (int r = 0; r < 4; r++) {
                int h = r >> 1, c = r & 1;
                float v = acc[mi][ni][r] * scale;
                if (diagBlk) {
                    int lr = warpM + mi * 16 + h * 8 + g;
                    int lc = warpN + ni * 8 + tig * 2 + c;
                    if (lr == lc) g_diag[row0 + lr] = v;
                }
                float e = __expf(v);
                rsum[mi * 2 + h] += e;
                csum[ni][c] += e;
            }

    #pragma unroll
    for (int k = 0; k < 4; k++) {
        rsum[k] += __shfl_xor_sync(0xffffffffu, rsum[k], 1);
        rsum[k] += __shfl_xor_sync(0xffffffffu, rsum[k], 2);
    }
    if (tig == 0) {
        #pragma unroll
        for (int k = 0; k < 4; k++) {
            int lr = warpM + (k >> 1) * 16 + (k & 1) * 8 + g;
            atomicAdd(&g_rowsum[row0 + lr], rsum[k]);
        }
    }
    #pragma unroll
    for (int ni = 0; ni < 8; ni++)
        #pragma unroll
        for (int c = 0; c < 2; c++) {
            csum[ni][c] += __shfl_xor_sync(0xffffffffu, csum[ni][c], 4);
            csum[ni][c] += __shfl_xor_sync(0xffffffffu, csum[ni][c], 8);
            csum[ni][c] += __shfl_xor_sync(0xffffffffu, csum[ni][c], 16);
        }
    if (lane < 4) {
        #pragma unroll
        for (int ni = 0; ni < 8; ni++)
            #pragma unroll
            for (int c = 0; c < 2; c++) {
                int lc = warpN + ni * 8 + lane * 2 + c;
                atomicAdd(&g_colsum[col0 + lc], csum[ni][c]);
            }
    }
}

// neg block: 32 negatives, 8 threads each; qid via binary search on g_off.
__device__ void neg_block(int negBlk, const float* __restrict__ q,
                          const float* __restrict__ nem,
                          const float* __restrict__ log_tau) {
    const int tid = threadIdx.x;
    const int neg = negBlk * 32 + (tid >> 3);
    const int l8  = tid & 7;

    // qid = max{ i : g_off[i] <= neg }  (12-step binary search, table L1/L2-hot)
    int lo = 0, hi = BATCH - 1;
    #pragma unroll
    for (int it = 0; it < 12; it++) {
        int mid = (lo + hi + 1) >> 1;
        if (__ldg(&g_off[mid]) <= neg) lo = mid; else hi = mid - 1;
    }
    const int qid = lo;

    const float4* nr = (const float4*)(nem + (size_t)neg * DIM);
    const float4* qr = (const float4*)(q   + (size_t)qid * DIM);

    float4 nv[8], qv[8];
    #pragma unroll
    for (int j = 0; j < 8; j++) nv[j] = nr[l8 + j * 8];
    #pragma unroll
    for (int j = 0; j < 8; j++) qv[j] = qr[l8 + j * 8];

    float dot = 0.f;
    #pragma unroll
    for (int j = 0; j < 8; j++)
        dot += qv[j].x * nv[j].x + qv[j].y * nv[j].y
             + qv[j].z * nv[j].z + qv[j].w * nv[j].w;
    dot += __shfl_xor_sync(0xffffffffu, dot, 1);
    dot += __shfl_xor_sync(0xffffffffu, dot, 2);
    dot += __shfl_xor_sync(0xffffffffu, dot, 4);
    if (l8 == 0)
        atomicAdd(&g_negsum[qid], __expf(dot * inv_tau(log_tau)));
}

__global__ __launch_bounds__(256, 2)
void fused_kernel(const float* __restrict__ q, const float* __restrict__ nem,
                  const float* __restrict__ log_tau, float* __restrict__ out)
{
    extern __shared__ char smem[];
    const int bid = blockIdx.x;
    if (bid & 1) {
        neg_block(bid >> 1, q, nem, log_tau);
    } else {
        sim_block(smem_u32(smem), bid >> 1, log_tau);
    }

    // ---- retirement: last block performs the final reduction ----
    __shared__ unsigned int s_old;
    __threadfence();
    __syncthreads();
    if (threadIdx.x == 0) s_old = atomicAdd(&g_done, 1u);
    __syncthreads();
    if (s_old != FUSED_BLOCKS - 1) return;

    __threadfence();
    float* sh = (float*)smem;     // block is done with its tile buffers
    int tid = threadIdx.x;
    float s = 0.f;
    for (int i = tid; i < BATCH; i += 256) {
        float d  = g_diag[i];
        float lq = logf(g_rowsum[i] + g_negsum[i]) - d;
        float lp = logf(g_colsum[i]) - d;
        s += 0.5f * (lq + lp);
    }
    sh[tid] = s;
    __syncthreads();
    #pragma unroll
    for (int off = 128; off >= 32; off >>= 1) {
        if (tid < off) sh[tid] += sh[tid + off];
        __syncthreads();
    }
    if (tid < 32) {
        float v = sh[tid];
        #pragma unroll
        for (int m = 16; m >= 1; m >>= 1)
            v += __shfl_xor_sync(0xffffffffu, v, m);
        if (tid == 0) out[0] = v / (float)BATCH;
    }
}

extern "C" void kernel_launch(void* const* d_in, const int* in_sizes, int n_in,
                              void* d_out, int out_size) {
    const float* q   = (const float*)d_in[0];
    const float* p   = (const float*)d_in[1];
    const float* nem = (const float*)d_in[2];
    const int*   cnt = (const int*)  d_in[3];
    const float* lt  = (const float*)d_in[4];
    float* out = (float*)d_out;

    cudaFuncSetAttribute(fused_kernel,
                         cudaFuncAttributeMaxDynamicSharedMemorySize, SM_TOTAL);

    convert_scan_kernel<<<257, 1024>>>(q, p, cnt);
    fused_kernel<<<FUSED_BLOCKS, 256, SM_TOTAL>>>(q, nem, lt, out);
}

// round 8
// speedup vs baseline: 1.1090x; 1.1090x over previous
#include <cuda_runtime.h>
#include <cuda_bf16.h>
#include <cstdint>

#define BATCH 4096
#define DIM   256
#define NNEG  32768

// ---------------- scratch (device globals; no allocs allowed) ----------------
__device__ float g_rowsum[BATCH];
__device__ float g_colsum[BATCH];
__device__ float g_negsum[BATCH];
__device__ float g_diag[BATCH];
__device__ int   g_off[BATCH];          // exclusive prefix of counts
__device__ __nv_bfloat16 g_qb[BATCH * DIM];
__device__ __nv_bfloat16 g_pb[BATCH * DIM];

__device__ __forceinline__ uint32_t smem_u32(const void* p) {
    uint32_t a;
    asm("{ .reg .u64 t; cvta.to.shared.u64 t, %1; cvt.u32.u64 %0, t; }" : "=r"(a) : "l"(p));
    return a;
}

__device__ __forceinline__ float inv_tau(const float* log_tau) {
    float t = expf(log_tau[0]);
    t = fminf(fmaxf(t, 1e-4f), 1.0f);
    return 1.0f / t;
}

// ---------------- setup: fp32->bf16 convert + zero + (block 256) offsets scan ----------------
// Blocks 0..255: 1024 threads, each converts one float4 of q and p.
// Block 256: 1024 threads compute exclusive-prefix offsets of counts.
__global__ void convert_scan_kernel(const float* __restrict__ q, const float* __restrict__ p,
                                    const int* __restrict__ counts) {
    int tid = threadIdx.x;
    if (blockIdx.x < 256) {
        int i = blockIdx.x * 1024 + tid;  // over BATCH*DIM/4 = 262144
        if (i < BATCH) { g_rowsum[i] = 0.f; g_colsum[i] = 0.f; g_negsum[i] = 0.f; }
        const float4 qa = ((const float4*)q)[i];
        const float4 pa = ((const float4*)p)[i];
        __nv_bfloat162* qd = (__nv_bfloat162*)g_qb;
        __nv_bfloat162* pd = (__nv_bfloat162*)g_pb;
        qd[i * 2 + 0] = __floats2bfloat162_rn(qa.x, qa.y);
        qd[i * 2 + 1] = __floats2bfloat162_rn(qa.z, qa.w);
        pd[i * 2 + 0] = __floats2bfloat162_rn(pa.x, pa.y);
        pd[i * 2 + 1] = __floats2bfloat162_rn(pa.z, pa.w);
        return;
    }
    // ---- scan block: offsets only, fully parallel ----
    __shared__ int wsum[32];
    int lane = tid & 31, w = tid >> 5;
    int4 c4 = ((const int4*)counts)[tid];          // counts[4t .. 4t+3]
    int run = c4.x + c4.y + c4.z + c4.w;
    int incl = run;
    #pragma unroll
    for (int m = 1; m < 32; m <<= 1) {
        int t = __shfl_up_sync(0xffffffffu, incl, m);
        if (lane >= m) incl += t;
    }
    if (lane == 31) wsum[w] = incl;
    __syncthreads();
    if (tid < 32) {
        int v = wsum[tid];
        int s = v;
        #pragma unroll
        for (int m = 1; m < 32; m <<= 1) {
            int t = __shfl_up_sync(0xffffffffu, s, m);
            if (tid >= m) s += t;
        }
        wsum[tid] = s - v;   // exclusive warp base
    }
    __syncthreads();
    int excl = incl - run + wsum[w];
    int4 o;
    o.x = excl;
    o.y = o.x + c4.x;
    o.z = o.y + c4.y;
    o.w = o.z + c4.z;
    ((int4*)g_off)[tid] = o;
}

// ---------------- fused sim(MMA) + neg kernel ----------------
// Even blockIdx -> sim 128x128 tile; odd blockIdx -> 32 negatives.
// K=256 in 4 chunks of 64, THREE-stage cp.async pipeline.
#define STRIDE     144
#define TILE_BYTES (128 * STRIDE)
#define BUF_BYTES  (2 * TILE_BYTES)      // A then B: 36864
#define SM_TOTAL   (3 * BUF_BYTES)       // 110592 (3 stages)

#define CP_COMMIT() asm volatile("cp.async.commit_group;" ::: "memory")

__device__ __forceinline__ void load_chunk(uint32_t sb, const char* qa, const char* pa,
                                           int chunk, int buf, int tid) {
    uint32_t base = sb + buf * BUF_BYTES;
    #pragma unroll
    for (int it = 0; it < 4; it++) {
        int idx = it * 256 + tid;
        int r = idx >> 3, s = idx & 7;
        uint32_t dst = base + r * STRIDE + s * 16;
        const char* srcA = qa + r * 512 + chunk * 128 + s * 16;
        const char* srcB = pa + r * 512 + chunk * 128 + s * 16;
        asm volatile("cp.async.cg.shared.global [%0], [%1], 16;" :: "r"(dst), "l"(srcA));
        asm volatile("cp.async.cg.shared.global [%0], [%1], 16;"
                     :: "r"(dst + TILE_BYTES), "l"(srcB));
    }
}

__device__ __forceinline__ void compute_chunk(uint32_t sb, int buf, int warpM, int warpN,
                                              int lane, float acc[2][8][4]) {
    uint32_t base  = sb + buf * BUF_BYTES;
    uint32_t aAddr = base + (uint32_t)(warpM + (lane & 15)) * STRIDE
                   + (uint32_t)(lane >> 4) * 16;
    uint32_t bAddr = base + TILE_BYTES
                   + (uint32_t)(warpN + (lane & 7) + ((lane >> 4) << 3)) * STRIDE
                   + (uint32_t)((lane >> 3) & 1) * 16;
    #pragma unroll
    for (int s = 0; s < 4; s++) {
        const uint32_t koff = (uint32_t)s * 32;
        uint32_t a[2][4];
        #pragma unroll
        for (int mi = 0; mi < 2; mi++) {
            asm volatile("ldmatrix.sync.aligned.m8n8.x4.shared.b16 {%0,%1,%2,%3}, [%4];"
                : "=r"(a[mi][0]), "=r"(a[mi][1]), "=r"(a[mi][2]), "=r"(a[mi][3])
                : "r"(aAddr + mi * (16 * STRIDE) + koff));
        }
        uint32_t b[4][4];
        #pragma unroll
        for (int nb = 0; nb < 4; nb++) {
            asm volatile("ldmatrix.sync.aligned.m8n8.x4.shared.b16 {%0,%1,%2,%3}, [%4];"
                : "=r"(b[nb][0]), "=r"(b[nb][1]), "=r"(b[nb][2]), "=r"(b[nb][3])
                : "r"(bAddr + nb * (16 * STRIDE) + koff));
        }
        #pragma unroll
        for (int mi = 0; mi < 2; mi++)
            #pragma unroll
            for (int nb = 0; nb < 4; nb++)
                #pragma unroll
                for (int sub = 0; sub < 2; sub++) {
                    float* d = acc[mi][nb * 2 + sub];
                    asm volatile(
                        "mma.sync.aligned.m16n8k16.row.col.f32.bf16.bf16.f32 "
                        "{%0,%1,%2,%3}, {%4,%5,%6,%7}, {%8,%9}, {%0,%1,%2,%3};"
                        : "+f"(d[0]), "+f"(d[1]), "+f"(d[2]), "+f"(d[3])
                        : "r"(a[mi][0]), "r"(a[mi][1]), "r"(a[mi][2]), "r"(a[mi][3]),
                          "r"(b[nb][sub * 2]), "r"(b[nb][sub * 2 + 1]));
                }
    }
}

__device__ void sim_block(uint32_t sb, int tileIdx, const float* __restrict__ log_tau) {
    const int tid  = threadIdx.x;
    const int wid  = tid >> 5;
    const int lane = tid & 31;
    const int row0 = (tileIdx >> 5) * 128;
    const int col0 = (tileIdx & 31) * 128;
    const int warpM = (wid >> 1) * 32;
    const int warpN = (wid & 1) * 64;

    const char* qa = (const char*)(g_qb + (size_t)row0 * DIM);
    const char* pa = (const char*)(g_pb + (size_t)col0 * DIM);

    float acc[2][8][4];
    #pragma unroll
    for (int mi = 0; mi < 2; mi++)
        #pragma unroll
        for (int ni = 0; ni < 8; ni++)
            #pragma unroll
            for (int r = 0; r < 4; r++) acc[mi][ni][r] = 0.f;

    // ---- 3-stage pipeline over 4 chunks ----
    load_chunk(sb, qa, pa, 0, 0, tid); CP_COMMIT();
    load_chunk(sb, qa, pa, 1, 1, tid); CP_COMMIT();
    load_chunk(sb, qa, pa, 2, 2, tid); CP_COMMIT();

    asm volatile("cp.async.wait_group 2;" ::: "memory");   // chunk 0 ready
    __syncthreads();
    compute_chunk(sb, 0, warpM, warpN, lane, acc);
    __syncthreads();                                        // buf0 free
    load_chunk(sb, qa, pa, 3, 0, tid); CP_COMMIT();

    asm volatile("cp.async.wait_group 2;" ::: "memory");   // chunk 1 ready
    __syncthreads();
    compute_chunk(sb, 1, warpM, warpN, lane, acc);

    asm volatile("cp.async.wait_group 1;" ::: "memory");   // chunk 2 ready
    __syncthreads();
    compute_chunk(sb, 2, warpM, warpN, lane, acc);

    asm volatile("cp.async.wait_group 0;" ::: "memory");   // chunk 3 ready
    __syncthreads();
    compute_chunk(sb, 0, warpM, warpN, lane, acc);

    // ---- epilogue ----
    const float scale = inv_tau(log_tau);
    const int g   = lane >> 2;
    const int tig = lane & 3;
    const bool diagBlk = (row0 == col0);

    float rsum[4];
    #pragma unroll
    for (int k = 0; k < 4; k++) rsum[k] = 0.f;
    float csum[8][2];
    #pragma unroll
    for (int ni = 0; ni < 8; ni++) { csum[ni][0] = 0.f; csum[ni][1] = 0.f; }

    #pragma unroll
    for (int mi = 0; mi < 2; mi++)
        #pragma unroll
        for (int ni = 0; ni < 8; ni++)
            #pragma unroll
            for (int r = 0; r < 4; r++) {
                int h = r >> 1, c = r & 1;
                float v = acc[mi][ni][r] * scale;
                if (diagBlk) {
                    int lr = warpM + mi * 16 + h * 8 + g;
                    int lc = warpN + ni * 8 + tig * 2 + c;
                    if (lr == lc) g_diag[row0 + lr] = v;
                }
                float e = __expf(v);
                rsum[mi * 2 + h] += e;
                csum[ni][c] += e;
            }

    #pragma unroll
    for (int k = 0; k < 4; k++) {
        rsum[k] += __shfl_xor_sync(0xffffffffu, rsum[k], 1);
        rsum[k] += __shfl_xor_sync(0xffffffffu, rsum[k], 2);
    }
    if (tig == 0) {
        #pragma unroll
        for (int k = 0; k < 4; k++) {
            int lr = warpM + (k >> 1) * 16 + (k & 1) * 8 + g;
            atomicAdd(&g_rowsum[row0 + lr], rsum[k]);
        }
    }
    #pragma unroll
    for (int ni = 0; ni < 8; ni++)
        #pragma unroll
        for (int c = 0; c < 2; c++) {
            csum[ni][c] += __shfl_xor_sync(0xffffffffu, csum[ni][c], 4);
            csum[ni][c] += __shfl_xor_sync(0xffffffffu, csum[ni][c], 8);
            csum[ni][c] += __shfl_xor_sync(0xffffffffu, csum[ni][c], 16);
        }
    if (lane < 4) {
        #pragma unroll
        for (int ni = 0; ni < 8; ni++)
            #pragma unroll
            for (int c = 0; c < 2; c++) {
                int lc = warpN + ni * 8 + lane * 2 + c;
                atomicAdd(&g_colsum[col0 + lc], csum[ni][c]);
            }
    }
}

// neg block: 32 negatives, 8 threads each; qid via binary search on g_off.
__device__ void neg_block(int negBlk, const float* __restrict__ q,
                          const float* __restrict__ nem,
                          const float* __restrict__ log_tau) {
    const int tid = threadIdx.x;
    const int neg = negBlk * 32 + (tid >> 3);
    const int l8  = tid & 7;

    // qid = max{ i : g_off[i] <= neg }  (12-step binary search, table L1/L2-hot)
    int lo = 0, hi = BATCH - 1;
    #pragma unroll
    for (int it = 0; it < 12; it++) {
        int mid = (lo + hi + 1) >> 1;
        if (__ldg(&g_off[mid]) <= neg) lo = mid; else hi = mid - 1;
    }
    const int qid = lo;

    const float4* nr = (const float4*)(nem + (size_t)neg * DIM);
    const float4* qr = (const float4*)(q   + (size_t)qid * DIM);

    float4 nv[8], qv[8];
    #pragma unroll
    for (int j = 0; j < 8; j++) nv[j] = nr[l8 + j * 8];
    #pragma unroll
    for (int j = 0; j < 8; j++) qv[j] = qr[l8 + j * 8];

    float dot = 0.f;
    #pragma unroll
    for (int j = 0; j < 8; j++)
        dot += qv[j].x * nv[j].x + qv[j].y * nv[j].y
             + qv[j].z * nv[j].z + qv[j].w * nv[j].w;
    dot += __shfl_xor_sync(0xffffffffu, dot, 1);
    dot += __shfl_xor_sync(0xffffffffu, dot, 2);
    dot += __shfl_xor_sync(0xffffffffu, dot, 4);
    if (l8 == 0)
        atomicAdd(&g_negsum[qid], __expf(dot * inv_tau(log_tau)));
}

__global__ __launch_bounds__(256, 2)
void fused_kernel(const float* __restrict__ q, const float* __restrict__ nem,
                  const float* __restrict__ log_tau)
{
    extern __shared__ char smem[];
    const int bid = blockIdx.x;
    if (bid & 1) {
        neg_block(bid >> 1, q, nem, log_tau);
    } else {
        sim_block(smem_u32(smem), bid >> 1, log_tau);
    }
}

// ---------------- finalize ----------------
__global__ void finalize_kernel(float* __restrict__ out) {
    __shared__ float sh[256];
    int tid = threadIdx.x;
    float s = 0.f;
    for (int i = tid; i < BATCH; i += 256) {
        float d  = g_diag[i];
        float lq = logf(g_rowsum[i] + g_negsum[i]) - d;
        float lp = logf(g_colsum[i]) - d;
        s += 0.5f * (lq + lp);
    }
    sh[tid] = s;
    __syncthreads();
    #pragma unroll
    for (int off = 128; off >= 32; off >>= 1) {
        if (tid < off) sh[tid] += sh[tid + off];
        __syncthreads();
    }
    if (tid < 32) {
        float v = sh[tid];
        #pragma unroll
        for (int m = 16; m >= 1; m >>= 1)
            v += __shfl_xor_sync(0xffffffffu, v, m);
        if (tid == 0) out[0] = v / (float)BATCH;
    }
}

extern "C" void kernel_launch(void* const* d_in, const int* in_sizes, int n_in,
                              void* d_out, int out_size) {
    const float* q   = (const float*)d_in[0];
    const float* p   = (const float*)d_in[1];
    const float* nem = (const float*)d_in[2];
    const int*   cnt = (const int*)  d_in[3];
    const float* lt  = (const float*)d_in[4];
    float* out = (float*)d_out;

    cudaFuncSetAttribute(fused_kernel,
                         cudaFuncAttributeMaxDynamicSharedMemorySize, SM_TOTAL);

    convert_scan_kernel<<<257, 1024>>>(q, p, cnt);
    fused_kernel<<<2048, 256, SM_TOTAL>>>(q, nem, lt);
    finalize_kernel<<<1, 256>>>(out);
}